// round 15
// baseline (speedup 1.0000x reference)
#include <cuda_runtime.h>
#include <cuda_bf16.h>
#include <cstdint>

// ---------------- problem constants ----------------
#define B_    4
#define QL_   1024
#define CL_   3072
#define KL_   4096      // CL + QL
#define H_    2048
#define NH_   16
#define NKV_  4
#define HD_   128
#define GROUPS_ 4       // NH / NKV

constexpr float EPS_   = 1e-6f;
constexpr float SCALE_ = 0.08838834764831845f; // 128^-0.5

// ---------------- scratch (device globals; no allocations allowed) ----------------
__device__ float g_qraw[(size_t)B_ * QL_ * NH_ * HD_];   // [B*QL, NH*HD]
__device__ float g_kraw[(size_t)B_ * KL_ * NKV_ * HD_];  // [B*KL, NKV*HD]
__device__ float g_vraw[(size_t)B_ * KL_ * NKV_ * HD_];  // [B*KL, NKV*HD]
__device__ float g_qn  [(size_t)B_ * NH_ * QL_ * HD_];   // [B, NH, QL, HD]
__device__ float g_kn  [(size_t)B_ * NKV_ * KL_ * HD_];  // [B, NKV, KL, HD]
__device__ float g_ao  [(size_t)B_ * QL_ * NH_ * HD_];   // [B*QL, NH*HD]

// ---------------- helpers ----------------
template <bool CONCAT>
__device__ __forceinline__ const float* a_rowptr(const float* __restrict__ A,
                                                 const float* __restrict__ ctx,
                                                 const float* __restrict__ noise,
                                                 int r) {
    if (!CONCAT) return A + (size_t)r * H_;
    int b = r >> 12;        // / KL_
    int p = r & (KL_ - 1);  // % KL_
    return (p < CL_) ? ctx + (size_t)(b * CL_ + p) * H_
                     : noise + (size_t)(b * QL_ + (p - CL_)) * H_;
}

__device__ __forceinline__ uint32_t f2tf32(float x) {
    uint32_t r;
    asm("cvt.rna.tf32.f32 %0, %1;" : "=r"(r) : "f"(x));
    return r;
}

__device__ __forceinline__ void splitf(float x, uint32_t& hi, uint32_t& lo) {
    hi = f2tf32(x);
    lo = f2tf32(x - __uint_as_float(hi));
}

__device__ __forceinline__ void mma_tf32(float* c, const uint32_t* a, const uint32_t* b) {
    asm volatile(
        "mma.sync.aligned.m16n8k8.row.col.f32.tf32.tf32.f32 "
        "{%0,%1,%2,%3}, {%4,%5,%6,%7}, {%8,%9}, {%0,%1,%2,%3};\n"
        : "+f"(c[0]), "+f"(c[1]), "+f"(c[2]), "+f"(c[3])
        : "r"(a[0]), "r"(a[1]), "r"(a[2]), "r"(a[3]), "r"(b[0]), "r"(b[1]));
}

// bf16 pair pack: result lower16 = bf16(x0), upper16 = bf16(x1)
__device__ __forceinline__ uint32_t packbf2(float x0, float x1) {
    uint32_t r;
    asm("cvt.rn.bf16x2.f32 %0, %1, %2;" : "=r"(r) : "f"(x1), "f"(x0));
    return r;
}
// split pair into hi/lo bf16x2 words
__device__ __forceinline__ void splitbf2(float x0, float x1, uint32_t& hi, uint32_t& lo) {
    hi = packbf2(x0, x1);
    float h0 = __uint_as_float(hi << 16);
    float h1 = __uint_as_float(hi & 0xffff0000u);
    lo = packbf2(x0 - h0, x1 - h1);
}

__device__ __forceinline__ void mma_bf16(float* c, const uint32_t* a, const uint32_t* b) {
    asm volatile(
        "mma.sync.aligned.m16n8k16.row.col.f32.bf16.bf16.f32 "
        "{%0,%1,%2,%3}, {%4,%5,%6,%7}, {%8,%9}, {%0,%1,%2,%3};\n"
        : "+f"(c[0]), "+f"(c[1]), "+f"(c[2]), "+f"(c[3])
        : "r"(a[0]), "r"(a[1]), "r"(a[2]), "r"(a[3]), "r"(b[0]), "r"(b[1]));
}

// ---------------- tf32 tensor-core GEMM (3xTF32 split => ~fp32 accuracy) ----------------
#define APAD 36
#define BPAD 132

template <bool CONCAT>
__global__ __launch_bounds__(256) void gemm_tf32_kernel(
    const float* __restrict__ A, const float* __restrict__ ctx,
    const float* __restrict__ noise, const float* __restrict__ W,
    float* __restrict__ C, int M, int N) {
    __shared__ float As[128 * APAD];
    __shared__ float Bs[32 * BPAD];

    const int tid  = threadIdx.x;
    const int lane = tid & 31;
    const int wid  = tid >> 5;
    const int warp_m = wid & 3;
    const int warp_n = wid >> 2;

    const int row0 = blockIdx.y * 128;
    const int col0 = blockIdx.x * 128;

    const int ka = (tid & 7) * 4;
    const int ar = tid >> 3;
    const int nb = (tid & 31) * 4;
    const int kb = tid >> 5;

    const float* arow[4];
#pragma unroll
    for (int i = 0; i < 4; i++)
        arow[i] = a_rowptr<CONCAT>(A, ctx, noise, row0 + ar + 32 * i);

    const int l4 = lane >> 2;
    const int lk = lane & 3;

    float acc[2][8][4];
#pragma unroll
    for (int mt = 0; mt < 2; mt++)
#pragma unroll
        for (int nt = 0; nt < 8; nt++)
#pragma unroll
            for (int c = 0; c < 4; c++) acc[mt][nt][c] = 0.0f;

    for (int k0 = 0; k0 < H_; k0 += 32) {
        float4 areg[4], breg[4];
#pragma unroll
        for (int i = 0; i < 4; i++)
            areg[i] = *(const float4*)(arow[i] + k0 + ka);
#pragma unroll
        for (int i = 0; i < 4; i++)
            breg[i] = *(const float4*)(W + (size_t)(k0 + kb + 8 * i) * N + col0 + nb);

        __syncthreads();
#pragma unroll
        for (int i = 0; i < 4; i++)
            *(float4*)&As[(ar + 32 * i) * APAD + ka] = areg[i];
#pragma unroll
        for (int i = 0; i < 4; i++)
            *(float4*)&Bs[(kb + 8 * i) * BPAD + nb] = breg[i];
        __syncthreads();

#pragma unroll
        for (int kk = 0; kk < 32; kk += 8) {
            uint32_t ahi[2][4], alo[2][4];
#pragma unroll
            for (int mt = 0; mt < 2; mt++) {
                int r0 = (warp_m * 32 + mt * 16 + l4) * APAD;
                int r1 = r0 + 8 * APAD;
                splitf(As[r0 + kk + lk],     ahi[mt][0], alo[mt][0]);
                splitf(As[r1 + kk + lk],     ahi[mt][1], alo[mt][1]);
                splitf(As[r0 + kk + lk + 4], ahi[mt][2], alo[mt][2]);
                splitf(As[r1 + kk + lk + 4], ahi[mt][3], alo[mt][3]);
            }
            uint32_t bhi[8][2], blo[8][2];
#pragma unroll
            for (int nt = 0; nt < 8; nt++) {
                int cn = warp_n * 64 + nt * 8 + l4;
                splitf(Bs[(kk + lk) * BPAD + cn],     bhi[nt][0], blo[nt][0]);
                splitf(Bs[(kk + lk + 4) * BPAD + cn], bhi[nt][1], blo[nt][1]);
            }
#pragma unroll
            for (int mt = 0; mt < 2; mt++)
#pragma unroll
                for (int nt = 0; nt < 8; nt++) {
                    mma_tf32(acc[mt][nt], ahi[mt], bhi[nt]);
                    mma_tf32(acc[mt][nt], ahi[mt], blo[nt]);
                    mma_tf32(acc[mt][nt], alo[mt], bhi[nt]);
                }
        }
    }

#pragma unroll
    for (int mt = 0; mt < 2; mt++) {
        int r0 = row0 + warp_m * 32 + mt * 16 + l4;
#pragma unroll
        for (int nt = 0; nt < 8; nt++) {
            int cn = col0 + warp_n * 64 + nt * 8 + 2 * lk;
            *(float2*)(C + (size_t)r0 * N + cn) = make_float2(acc[mt][nt][0], acc[mt][nt][1]);
            *(float2*)(C + (size_t)(r0 + 8) * N + cn) = make_float2(acc[mt][nt][2], acc[mt][nt][3]);
        }
    }
}

// ---------------- RMSNorm + RoPE ----------------
__device__ __forceinline__ float block_sum128(float v, float* red) {
#pragma unroll
    for (int o = 16; o; o >>= 1) v += __shfl_xor_sync(0xffffffffu, v, o);
    if ((threadIdx.x & 31) == 0) red[threadIdx.x >> 5] = v;
    __syncthreads();
    return red[0] + red[1] + red[2] + red[3];
}

__global__ __launch_bounds__(128) void qnorm_rope_kernel(
    const float* __restrict__ qraw, const float* __restrict__ cosT,
    const float* __restrict__ sinT, const float* __restrict__ w,
    float* __restrict__ qout) {
    __shared__ float red[4];
    __shared__ float sx[128];
    const int blk = blockIdx.x;
    const int h   = blk & (NH_ - 1);
    const int row = blk >> 4;
    const int b   = row >> 10;
    const int qi  = row & (QL_ - 1);
    const int t   = threadIdx.x;

    float x = qraw[(size_t)row * (NH_ * HD_) + h * HD_ + t];
    float ss = block_sum128(x * x, red);
    float inv = rsqrtf(ss * (1.0f / HD_) + EPS_);
    float xn = x * inv * w[t];
    sx[t] = xn;
    __syncthreads();
    float rot = (t < 64) ? -sx[t + 64] : sx[t - 64];
    int pos = CL_ + qi;
    size_t ci = ((size_t)b * KL_ + pos) * HD_ + t;
    float outv = xn * cosT[ci] + rot * sinT[ci];
    qout[(((size_t)(b * NH_ + h) * QL_) + qi) * HD_ + t] = outv;
}

__global__ __launch_bounds__(128) void knorm_rope_kernel(
    const float* __restrict__ kraw, const float* __restrict__ cosT,
    const float* __restrict__ sinT, const float* __restrict__ w,
    float* __restrict__ kout) {
    __shared__ float red[4];
    __shared__ float sx[128];
    const int blk = blockIdx.x;
    const int kvh = blk & (NKV_ - 1);
    const int row = blk >> 2;
    const int b   = row >> 12;
    const int p   = row & (KL_ - 1);
    const int t   = threadIdx.x;

    float x = kraw[(size_t)row * (NKV_ * HD_) + kvh * HD_ + t];
    float ss = block_sum128(x * x, red);
    float inv = rsqrtf(ss * (1.0f / HD_) + EPS_);
    float xn = x * inv * w[t];
    sx[t] = xn;
    __syncthreads();
    float rot = (t < 64) ? -sx[t + 64] : sx[t - 64];
    size_t ci = ((size_t)b * KL_ + p) * HD_ + t;
    float outv = xn * cosT[ci] + rot * sinT[ci];
    kout[(((size_t)(b * NKV_ + kvh) * KL_) + p) * HD_ + t] = outv;
}

// ---------------- bf16x3 tensor-core flash attention (v3) ----------------
// Block: 256 thr = 8 warps. Tile: 128 q x 64 k. Warp w owns q rows [w*16, w*16+16).
// Register-resident P (S C-frag == PV A-frag layout; validated R13).
// K/V register double-buffer: next tile's LDGs issued right after the store
// barrier, overlapping global latency with the mma phase.
// Strides (words) all ≡ 4 (mod 32) => conflict-free fragment LDS.
constexpr int QW = 68;   // Q plane row stride (words)
constexpr int KW = 68;   // K plane row stride
constexpr int VW = 36;   // V^T plane row stride
constexpr int FLASH_SMEM = (2 * 128 * QW + 2 * 64 * KW + 2 * 128 * VW) * 4; // 141312 B

__global__ __launch_bounds__(256, 1) void flash_bf16_kernel(
    const float* __restrict__ q, const float* __restrict__ k,
    const float* __restrict__ vraw, float* __restrict__ o) {
    extern __shared__ uint32_t smu[];
    uint32_t* Qhi = smu;
    uint32_t* Qlo = Qhi + 128 * QW;
    uint32_t* Khi = Qlo + 128 * QW;
    uint32_t* Klo = Khi + 64 * KW;
    uint32_t* Vhi = Klo + 64 * KW;     // V^T: [128 dims][VW]
    uint32_t* Vlo = Vhi + 128 * VW;

    const int b   = blockIdx.z;
    const int h   = blockIdx.y;
    const int q0  = blockIdx.x * 128;
    const int kvh = h >> 2;
    const int tid = threadIdx.x;
    const int lane = tid & 31;
    const int w    = tid >> 5;
    const int l4   = lane >> 2;
    const int lk   = lane & 3;

    const float* kbase = k + (size_t)(b * NKV_ + kvh) * KL_ * HD_;
    const float4* vbase4 = (const float4*)vraw;

    // per-thread K/V load coordinates (i = tid + 256*j)
    // K: row = i>>5 (0..63), col4 = i&31 ; V: key = i&63, dimgroup = i>>6
    float4 kreg[8], vreg[8];
#pragma unroll
    for (int j = 0; j < 8; j++) {
        int i = tid + 256 * j;
        kreg[j] = *(const float4*)(kbase + (size_t)(i >> 5) * HD_ + 4 * (i & 31));
        vreg[j] = vbase4[(size_t)(b * KL_ + (i & 63)) * 128 + kvh * 32 + (i >> 6)];
    }

    // ---- load Q tile [128,128]: scale, split into bf16 hi/lo planes ----
    const float4* qsrc = (const float4*)(q + (((size_t)(b * NH_ + h) * QL_ + q0) * HD_));
    for (int i = tid; i < 128 * 32; i += 256) {
        int r = i >> 5, c = i & 31;
        float4 v = qsrc[i];
        uint32_t h0, l0, h1, l1;
        splitbf2(v.x * SCALE_, v.y * SCALE_, h0, l0);
        splitbf2(v.z * SCALE_, v.w * SCALE_, h1, l1);
        *(uint2*)&Qhi[r * QW + 2 * c] = make_uint2(h0, h1);
        *(uint2*)&Qlo[r * QW + 2 * c] = make_uint2(l0, l1);
    }

    float mA = -3.0e38f, mB = -3.0e38f, lA = 0.0f, lB = 0.0f;
    float O[16][4];
#pragma unroll
    for (int nt = 0; nt < 16; nt++)
#pragma unroll
        for (int c = 0; c < 4; c++) O[nt][c] = 0.0f;

    const int rowA = w * 16 + l4;
    const int rowB = rowA + 8;

    for (int k0 = 0; k0 < KL_; k0 += 64) {
        __syncthreads();   // smem free (prev tile consumed; 1st iter: Q store visible too)
        // ---- store K tile from regs -> hi/lo planes ----
#pragma unroll
        for (int j = 0; j < 8; j++) {
            int i = tid + 256 * j;
            int r = i >> 5, c = i & 31;
            uint32_t h0, l0, h1, l1;
            splitbf2(kreg[j].x, kreg[j].y, h0, l0);
            splitbf2(kreg[j].z, kreg[j].w, h1, l1);
            *(uint2*)&Khi[r * KW + 2 * c] = make_uint2(h0, h1);
            *(uint2*)&Klo[r * KW + 2 * c] = make_uint2(l0, l1);
        }
        // ---- store V tile transposed from regs: V^T[dim][key] hi/lo planes ----
#pragma unroll
        for (int j = 0; j < 8; j++) {
            int i = tid + 256 * j;
            int key = i & 63, dg = i >> 6;
            float vals[4] = {vreg[j].x, vreg[j].y, vreg[j].z, vreg[j].w};
#pragma unroll
            for (int jj = 0; jj < 4; jj++) {
                __nv_bfloat16 hb = __float2bfloat16(vals[jj]);
                __nv_bfloat16 lb = __float2bfloat16(vals[jj] - __bfloat162float(hb));
                ((__nv_bfloat16*)Vhi)[(size_t)(4 * dg + jj) * (2 * VW) + key] = hb;
                ((__nv_bfloat16*)Vlo)[(size_t)(4 * dg + jj) * (2 * VW) + key] = lb;
            }
        }
        __syncthreads();

        // ---- prefetch next tile's K/V into regs (overlaps with mma phase) ----
        if (k0 + 64 < KL_) {
#pragma unroll
            for (int j = 0; j < 8; j++) {
                int i = tid + 256 * j;
                kreg[j] = *(const float4*)(kbase + (size_t)(k0 + 64 + (i >> 5)) * HD_ + 4 * (i & 31));
                vreg[j] = vbase4[(size_t)(b * KL_ + k0 + 64 + (i & 63)) * 128 + kvh * 32 + (i >> 6)];
            }
        }

        // ---- S = Q @ K^T (16 x 64 per warp), 3xBF16 ----
        float Sf[8][4];
#pragma unroll
        for (int nt = 0; nt < 8; nt++)
#pragma unroll
            for (int c = 0; c < 4; c++) Sf[nt][c] = 0.0f;

#pragma unroll
        for (int kk = 0; kk < 8; kk++) {     // k=16 per step over HD=128
            const int c0 = kk * 8 + lk;
            uint32_t aH[4], aL[4];
            aH[0] = Qhi[rowA * QW + c0];     aL[0] = Qlo[rowA * QW + c0];
            aH[1] = Qhi[rowB * QW + c0];     aL[1] = Qlo[rowB * QW + c0];
            aH[2] = Qhi[rowA * QW + c0 + 4]; aL[2] = Qlo[rowA * QW + c0 + 4];
            aH[3] = Qhi[rowB * QW + c0 + 4]; aL[3] = Qlo[rowB * QW + c0 + 4];
#pragma unroll
            for (int nt = 0; nt < 8; nt++) {
                const int kr = (nt * 8 + l4) * KW + c0;
                uint32_t bH[2], bL[2];
                bH[0] = Khi[kr];     bH[1] = Khi[kr + 4];
                bL[0] = Klo[kr];     bL[1] = Klo[kr + 4];
                mma_bf16(Sf[nt], aH, bH);
                mma_bf16(Sf[nt], aL, bH);
                mma_bf16(Sf[nt], aH, bL);
            }
        }

        // ---- online softmax (warp-local; rows rowA / rowB) ----
        float mxA = Sf[0][0], mxB = Sf[0][2];
#pragma unroll
        for (int nt = 0; nt < 8; nt++) {
            mxA = fmaxf(mxA, fmaxf(Sf[nt][0], Sf[nt][1]));
            mxB = fmaxf(mxB, fmaxf(Sf[nt][2], Sf[nt][3]));
        }
        mxA = fmaxf(mxA, __shfl_xor_sync(0xffffffffu, mxA, 1));
        mxA = fmaxf(mxA, __shfl_xor_sync(0xffffffffu, mxA, 2));
        mxB = fmaxf(mxB, __shfl_xor_sync(0xffffffffu, mxB, 1));
        mxB = fmaxf(mxB, __shfl_xor_sync(0xffffffffu, mxB, 2));

        float mnA = fmaxf(mA, mxA), mnB = fmaxf(mB, mxB);
        float cA = __expf(mA - mnA), cB = __expf(mB - mnB);
        mA = mnA; mB = mnB;

        // ---- exp + pack P straight into bf16x2 hi/lo A-fragments ----
        uint32_t pH[8][2], pL[8][2];
        float sA = 0.0f, sB = 0.0f;
#pragma unroll
        for (int nt = 0; nt < 8; nt++) {
            float p0 = __expf(Sf[nt][0] - mnA), p1 = __expf(Sf[nt][1] - mnA);
            float p2 = __expf(Sf[nt][2] - mnB), p3 = __expf(Sf[nt][3] - mnB);
            sA += p0 + p1; sB += p2 + p3;
            splitbf2(p0, p1, pH[nt][0], pL[nt][0]);   // row l4
            splitbf2(p2, p3, pH[nt][1], pL[nt][1]);   // row l4+8
        }
        sA += __shfl_xor_sync(0xffffffffu, sA, 1);
        sA += __shfl_xor_sync(0xffffffffu, sA, 2);
        sB += __shfl_xor_sync(0xffffffffu, sB, 1);
        sB += __shfl_xor_sync(0xffffffffu, sB, 2);
        lA = lA * cA + sA;
        lB = lB * cB + sB;

#pragma unroll
        for (int nt = 0; nt < 16; nt++) {
            O[nt][0] *= cA; O[nt][1] *= cA;
            O[nt][2] *= cB; O[nt][3] *= cB;
        }

        // ---- O += P @ V (16 x 128 per warp), 3xBF16, P from registers ----
#pragma unroll
        for (int kt = 0; kt < 4; kt++) {     // 16 keys per step
            uint32_t aH[4], aL[4];
            aH[0] = pH[2 * kt][0];     aL[0] = pL[2 * kt][0];
            aH[1] = pH[2 * kt][1];     aL[1] = pL[2 * kt][1];
            aH[2] = pH[2 * kt + 1][0]; aL[2] = pL[2 * kt + 1][0];
            aH[3] = pH[2 * kt + 1][1]; aL[3] = pL[2 * kt + 1][1];
            const int ck = kt * 8 + lk;
#pragma unroll
            for (int nt = 0; nt < 16; nt++) {
                const int vr = (nt * 8 + l4) * VW + ck;
                uint32_t vH[2], vL[2];
                vH[0] = Vhi[vr];     vH[1] = Vhi[vr + 4];
                vL[0] = Vlo[vr];     vL[1] = Vlo[vr + 4];
                mma_bf16(O[nt], aH, vH);
                mma_bf16(O[nt], aL, vH);
                mma_bf16(O[nt], aH, vL);
            }
        }
    }

    // ---- epilogue: O /= l, write [B*QL, NH*HD] ----
    float iA = 1.0f / lA, iB = 1.0f / lB;
    float* obase = o + ((size_t)(b * QL_ + q0 + rowA)) * (NH_ * HD_) + h * HD_;
#pragma unroll
    for (int nt = 0; nt < 16; nt++) {
        *(float2*)(obase + nt * 8 + 2 * lk) =
            make_float2(O[nt][0] * iA, O[nt][1] * iA);
        *(float2*)(obase + (size_t)8 * (NH_ * HD_) + nt * 8 + 2 * lk) =
            make_float2(O[nt][2] * iB, O[nt][3] * iB);
    }
}

// ---------------- launch ----------------
extern "C" void kernel_launch(void* const* d_in, const int* in_sizes, int n_in,
                              void* d_out, int out_size) {
    const float* noise = (const float*)d_in[0];
    const float* ctx   = (const float*)d_in[1];
    const float* cosT  = (const float*)d_in[2];
    const float* sinT  = (const float*)d_in[3];
    const float* Wq    = (const float*)d_in[4];
    const float* Wk    = (const float*)d_in[5];
    const float* Wv    = (const float*)d_in[6];
    const float* Wo    = (const float*)d_in[7];
    const float* qnw   = (const float*)d_in[8];
    const float* knw   = (const float*)d_in[9];
    float* out = (float*)d_out;

    float *qraw, *kraw, *vraw, *qn, *kn, *ao;
    cudaGetSymbolAddress((void**)&qraw, g_qraw);
    cudaGetSymbolAddress((void**)&kraw, g_kraw);
    cudaGetSymbolAddress((void**)&vraw, g_vraw);
    cudaGetSymbolAddress((void**)&qn,   g_qn);
    cudaGetSymbolAddress((void**)&kn,   g_kn);
    cudaGetSymbolAddress((void**)&ao,   g_ao);

    cudaFuncSetAttribute(flash_bf16_kernel, cudaFuncAttributeMaxDynamicSharedMemorySize,
                         FLASH_SMEM);

    // projections (tf32 tensor cores, 3xTF32 split)
    gemm_tf32_kernel<false><<<dim3(16, 32), 256>>>(noise, nullptr, nullptr, Wq, qraw,
                                                   B_ * QL_, NH_ * HD_);
    gemm_tf32_kernel<true><<<dim3(4, 128), 256>>>(nullptr, ctx, noise, Wk, kraw,
                                                  B_ * KL_, NKV_ * HD_);
    gemm_tf32_kernel<true><<<dim3(4, 128), 256>>>(nullptr, ctx, noise, Wv, vraw,
                                                  B_ * KL_, NKV_ * HD_);
    // norm + rope
    qnorm_rope_kernel<<<B_ * QL_ * NH_, 128>>>(qraw, cosT, sinT, qnw, qn);
    knorm_rope_kernel<<<B_ * KL_ * NKV_, 128>>>(kraw, cosT, sinT, knw, kn);
    // attention (bf16x3, 128q tile, register P, K/V register prefetch)
    flash_bf16_kernel<<<dim3(QL_ / 128, NH_, B_), 256, FLASH_SMEM>>>(qn, kn, vraw, ao);
    // output projection
    gemm_tf32_kernel<false><<<dim3(16, 32), 256>>>(ao, nullptr, nullptr, Wo, out,
                                                   B_ * QL_, NH_ * HD_);
}

// round 16
// speedup vs baseline: 1.3924x; 1.3924x over previous
#include <cuda_runtime.h>
#include <cuda_bf16.h>
#include <cstdint>

// ---------------- problem constants ----------------
#define B_    4
#define QL_   1024
#define CL_   3072
#define KL_   4096      // CL + QL
#define H_    2048
#define NH_   16
#define NKV_  4
#define HD_   128
#define GROUPS_ 4       // NH / NKV

constexpr float EPS_   = 1e-6f;
constexpr float SCALE_ = 0.08838834764831845f; // 128^-0.5

// ---------------- scratch (device globals; no allocations allowed) ----------------
__device__ float g_qraw[(size_t)B_ * QL_ * NH_ * HD_];   // [B*QL, NH*HD]
__device__ float g_kraw[(size_t)B_ * KL_ * NKV_ * HD_];  // [B*KL, NKV*HD]
__device__ float g_vraw[(size_t)B_ * KL_ * NKV_ * HD_];  // [B*KL, NKV*HD]
__device__ float g_qn  [(size_t)B_ * NH_ * QL_ * HD_];   // [B, NH, QL, HD]
__device__ float g_kn  [(size_t)B_ * NKV_ * KL_ * HD_];  // [B, NKV, KL, HD]
__device__ float g_ao  [(size_t)B_ * QL_ * NH_ * HD_];   // [B*QL, NH*HD]

// ---------------- helpers ----------------
template <bool CONCAT>
__device__ __forceinline__ const float* a_rowptr(const float* __restrict__ A,
                                                 const float* __restrict__ ctx,
                                                 const float* __restrict__ noise,
                                                 int r) {
    if (!CONCAT) return A + (size_t)r * H_;
    int b = r >> 12;        // / KL_
    int p = r & (KL_ - 1);  // % KL_
    return (p < CL_) ? ctx + (size_t)(b * CL_ + p) * H_
                     : noise + (size_t)(b * QL_ + (p - CL_)) * H_;
}

__device__ __forceinline__ uint32_t f2tf32(float x) {
    uint32_t r;
    asm("cvt.rna.tf32.f32 %0, %1;" : "=r"(r) : "f"(x));
    return r;
}

__device__ __forceinline__ void splitf(float x, uint32_t& hi, uint32_t& lo) {
    hi = f2tf32(x);
    lo = f2tf32(x - __uint_as_float(hi));
}

__device__ __forceinline__ void mma_tf32(float* c, const uint32_t* a, const uint32_t* b) {
    asm volatile(
        "mma.sync.aligned.m16n8k8.row.col.f32.tf32.tf32.f32 "
        "{%0,%1,%2,%3}, {%4,%5,%6,%7}, {%8,%9}, {%0,%1,%2,%3};\n"
        : "+f"(c[0]), "+f"(c[1]), "+f"(c[2]), "+f"(c[3])
        : "r"(a[0]), "r"(a[1]), "r"(a[2]), "r"(a[3]), "r"(b[0]), "r"(b[1]));
}

// bf16 pair pack: result lower16 = bf16(x0), upper16 = bf16(x1)
__device__ __forceinline__ uint32_t packbf2(float x0, float x1) {
    uint32_t r;
    asm("cvt.rn.bf16x2.f32 %0, %1, %2;" : "=r"(r) : "f"(x1), "f"(x0));
    return r;
}
// split pair into hi/lo bf16x2 words
__device__ __forceinline__ void splitbf2(float x0, float x1, uint32_t& hi, uint32_t& lo) {
    hi = packbf2(x0, x1);
    float h0 = __uint_as_float(hi << 16);
    float h1 = __uint_as_float(hi & 0xffff0000u);
    lo = packbf2(x0 - h0, x1 - h1);
}

__device__ __forceinline__ void mma_bf16(float* c, const uint32_t* a, const uint32_t* b) {
    asm volatile(
        "mma.sync.aligned.m16n8k16.row.col.f32.bf16.bf16.f32 "
        "{%0,%1,%2,%3}, {%4,%5,%6,%7}, {%8,%9}, {%0,%1,%2,%3};\n"
        : "+f"(c[0]), "+f"(c[1]), "+f"(c[2]), "+f"(c[3])
        : "r"(a[0]), "r"(a[1]), "r"(a[2]), "r"(a[3]), "r"(b[0]), "r"(b[1]));
}

// ---------------- tf32 tensor-core GEMM (3xTF32 split => ~fp32 accuracy) ----------------
#define APAD 36
#define BPAD 132

template <bool CONCAT>
__global__ __launch_bounds__(256) void gemm_tf32_kernel(
    const float* __restrict__ A, const float* __restrict__ ctx,
    const float* __restrict__ noise, const float* __restrict__ W,
    float* __restrict__ C, int M, int N) {
    __shared__ float As[128 * APAD];
    __shared__ float Bs[32 * BPAD];

    const int tid  = threadIdx.x;
    const int lane = tid & 31;
    const int wid  = tid >> 5;
    const int warp_m = wid & 3;
    const int warp_n = wid >> 2;

    const int row0 = blockIdx.y * 128;
    const int col0 = blockIdx.x * 128;

    const int ka = (tid & 7) * 4;
    const int ar = tid >> 3;
    const int nb = (tid & 31) * 4;
    const int kb = tid >> 5;

    const float* arow[4];
#pragma unroll
    for (int i = 0; i < 4; i++)
        arow[i] = a_rowptr<CONCAT>(A, ctx, noise, row0 + ar + 32 * i);

    const int l4 = lane >> 2;
    const int lk = lane & 3;

    float acc[2][8][4];
#pragma unroll
    for (int mt = 0; mt < 2; mt++)
#pragma unroll
        for (int nt = 0; nt < 8; nt++)
#pragma unroll
            for (int c = 0; c < 4; c++) acc[mt][nt][c] = 0.0f;

    for (int k0 = 0; k0 < H_; k0 += 32) {
        float4 areg[4], breg[4];
#pragma unroll
        for (int i = 0; i < 4; i++)
            areg[i] = *(const float4*)(arow[i] + k0 + ka);
#pragma unroll
        for (int i = 0; i < 4; i++)
            breg[i] = *(const float4*)(W + (size_t)(k0 + kb + 8 * i) * N + col0 + nb);

        __syncthreads();
#pragma unroll
        for (int i = 0; i < 4; i++)
            *(float4*)&As[(ar + 32 * i) * APAD + ka] = areg[i];
#pragma unroll
        for (int i = 0; i < 4; i++)
            *(float4*)&Bs[(kb + 8 * i) * BPAD + nb] = breg[i];
        __syncthreads();

#pragma unroll
        for (int kk = 0; kk < 32; kk += 8) {
            uint32_t ahi[2][4], alo[2][4];
#pragma unroll
            for (int mt = 0; mt < 2; mt++) {
                int r0 = (warp_m * 32 + mt * 16 + l4) * APAD;
                int r1 = r0 + 8 * APAD;
                splitf(As[r0 + kk + lk],     ahi[mt][0], alo[mt][0]);
                splitf(As[r1 + kk + lk],     ahi[mt][1], alo[mt][1]);
                splitf(As[r0 + kk + lk + 4], ahi[mt][2], alo[mt][2]);
                splitf(As[r1 + kk + lk + 4], ahi[mt][3], alo[mt][3]);
            }
            uint32_t bhi[8][2], blo[8][2];
#pragma unroll
            for (int nt = 0; nt < 8; nt++) {
                int cn = warp_n * 64 + nt * 8 + l4;
                splitf(Bs[(kk + lk) * BPAD + cn],     bhi[nt][0], blo[nt][0]);
                splitf(Bs[(kk + lk + 4) * BPAD + cn], bhi[nt][1], blo[nt][1]);
            }
#pragma unroll
            for (int mt = 0; mt < 2; mt++)
#pragma unroll
                for (int nt = 0; nt < 8; nt++) {
                    mma_tf32(acc[mt][nt], ahi[mt], bhi[nt]);
                    mma_tf32(acc[mt][nt], ahi[mt], blo[nt]);
                    mma_tf32(acc[mt][nt], alo[mt], bhi[nt]);
                }
        }
    }

#pragma unroll
    for (int mt = 0; mt < 2; mt++) {
        int r0 = row0 + warp_m * 32 + mt * 16 + l4;
#pragma unroll
        for (int nt = 0; nt < 8; nt++) {
            int cn = col0 + warp_n * 64 + nt * 8 + 2 * lk;
            *(float2*)(C + (size_t)r0 * N + cn) = make_float2(acc[mt][nt][0], acc[mt][nt][1]);
            *(float2*)(C + (size_t)(r0 + 8) * N + cn) = make_float2(acc[mt][nt][2], acc[mt][nt][3]);
        }
    }
}

// ---------------- RMSNorm + RoPE ----------------
__device__ __forceinline__ float block_sum128(float v, float* red) {
#pragma unroll
    for (int o = 16; o; o >>= 1) v += __shfl_xor_sync(0xffffffffu, v, o);
    if ((threadIdx.x & 31) == 0) red[threadIdx.x >> 5] = v;
    __syncthreads();
    return red[0] + red[1] + red[2] + red[3];
}

__global__ __launch_bounds__(128) void qnorm_rope_kernel(
    const float* __restrict__ qraw, const float* __restrict__ cosT,
    const float* __restrict__ sinT, const float* __restrict__ w,
    float* __restrict__ qout) {
    __shared__ float red[4];
    __shared__ float sx[128];
    const int blk = blockIdx.x;
    const int h   = blk & (NH_ - 1);
    const int row = blk >> 4;
    const int b   = row >> 10;
    const int qi  = row & (QL_ - 1);
    const int t   = threadIdx.x;

    float x = qraw[(size_t)row * (NH_ * HD_) + h * HD_ + t];
    float ss = block_sum128(x * x, red);
    float inv = rsqrtf(ss * (1.0f / HD_) + EPS_);
    float xn = x * inv * w[t];
    sx[t] = xn;
    __syncthreads();
    float rot = (t < 64) ? -sx[t + 64] : sx[t - 64];
    int pos = CL_ + qi;
    size_t ci = ((size_t)b * KL_ + pos) * HD_ + t;
    float outv = xn * cosT[ci] + rot * sinT[ci];
    qout[(((size_t)(b * NH_ + h) * QL_) + qi) * HD_ + t] = outv;
}

__global__ __launch_bounds__(128) void knorm_rope_kernel(
    const float* __restrict__ kraw, const float* __restrict__ cosT,
    const float* __restrict__ sinT, const float* __restrict__ w,
    float* __restrict__ kout) {
    __shared__ float red[4];
    __shared__ float sx[128];
    const int blk = blockIdx.x;
    const int kvh = blk & (NKV_ - 1);
    const int row = blk >> 2;
    const int b   = row >> 12;
    const int p   = row & (KL_ - 1);
    const int t   = threadIdx.x;

    float x = kraw[(size_t)row * (NKV_ * HD_) + kvh * HD_ + t];
    float ss = block_sum128(x * x, red);
    float inv = rsqrtf(ss * (1.0f / HD_) + EPS_);
    float xn = x * inv * w[t];
    sx[t] = xn;
    __syncthreads();
    float rot = (t < 64) ? -sx[t + 64] : sx[t - 64];
    size_t ci = ((size_t)b * KL_ + p) * HD_ + t;
    float outv = xn * cosT[ci] + rot * sinT[ci];
    kout[(((size_t)(b * NKV_ + kvh) * KL_) + p) * HD_ + t] = outv;
}

// ---------------- bf16x3 tensor-core flash attention (v4 = R12 + register P) ----------------
// Block: 256 thr = 8 warps. Tile: 128 q x 64 k. Warp w owns q rows [w*16, w*16+16).
// K/V loaded gmem -> split -> smem each tile (R12 structure, proven 5081us).
// P never touches smem: S C-fragment == PV A-fragment layout (validated R13/R15,
// bit-identical rel_err). smem 141,312 B, 1 CTA/SM.
// Strides (words) all ≡ 4 (mod 32) => conflict-free fragment LDS.
constexpr int QW = 68;   // Q plane row stride (words)
constexpr int KW = 68;   // K plane row stride
constexpr int VW = 36;   // V^T plane row stride
constexpr int FLASH_SMEM = (2 * 128 * QW + 2 * 64 * KW + 2 * 128 * VW) * 4; // 141312 B

__global__ __launch_bounds__(256, 1) void flash_bf16_kernel(
    const float* __restrict__ q, const float* __restrict__ k,
    const float* __restrict__ vraw, float* __restrict__ o) {
    extern __shared__ uint32_t smu[];
    uint32_t* Qhi = smu;
    uint32_t* Qlo = Qhi + 128 * QW;
    uint32_t* Khi = Qlo + 128 * QW;
    uint32_t* Klo = Khi + 64 * KW;
    uint32_t* Vhi = Klo + 64 * KW;     // V^T: [128 dims][VW]
    uint32_t* Vlo = Vhi + 128 * VW;

    const int b   = blockIdx.z;
    const int h   = blockIdx.y;
    const int q0  = blockIdx.x * 128;
    const int kvh = h >> 2;
    const int tid = threadIdx.x;
    const int lane = tid & 31;
    const int w    = tid >> 5;
    const int l4   = lane >> 2;
    const int lk   = lane & 3;

    // ---- load Q tile [128,128]: scale, split into bf16 hi/lo planes ----
    const float4* qsrc = (const float4*)(q + (((size_t)(b * NH_ + h) * QL_ + q0) * HD_));
    for (int i = tid; i < 128 * 32; i += 256) {
        int r = i >> 5, c = i & 31;
        float4 v = qsrc[i];
        uint32_t h0, l0, h1, l1;
        splitbf2(v.x * SCALE_, v.y * SCALE_, h0, l0);
        splitbf2(v.z * SCALE_, v.w * SCALE_, h1, l1);
        *(uint2*)&Qhi[r * QW + 2 * c] = make_uint2(h0, h1);
        *(uint2*)&Qlo[r * QW + 2 * c] = make_uint2(l0, l1);
    }

    float mA = -3.0e38f, mB = -3.0e38f, lA = 0.0f, lB = 0.0f;
    float O[16][4];
#pragma unroll
    for (int nt = 0; nt < 16; nt++)
#pragma unroll
        for (int c = 0; c < 4; c++) O[nt][c] = 0.0f;

    const float* kbase = k + (size_t)(b * NKV_ + kvh) * KL_ * HD_;
    const float4* vbase4 = (const float4*)vraw;

    const int rowA = w * 16 + l4;
    const int rowB = rowA + 8;

    for (int k0 = 0; k0 < KL_; k0 += 64) {
        __syncthreads();
        // ---- K tile [64 keys][128 dims] -> hi/lo planes ----
        for (int i = tid; i < 64 * 32; i += 256) {
            int r = i >> 5, c = i & 31;
            float4 kv = *(const float4*)(kbase + (size_t)(k0 + r) * HD_ + 4 * c);
            uint32_t h0, l0, h1, l1;
            splitbf2(kv.x, kv.y, h0, l0);
            splitbf2(kv.z, kv.w, h1, l1);
            *(uint2*)&Khi[r * KW + 2 * c] = make_uint2(h0, h1);
            *(uint2*)&Klo[r * KW + 2 * c] = make_uint2(l0, l1);
        }
        // ---- V tile transposed: V^T[dim][key] hi/lo planes ----
        for (int i = tid; i < 64 * 32; i += 256) {
            int key = i & 63, dg = i >> 6;   // dg: dim group of 4
            float4 vv = vbase4[(size_t)(b * KL_ + k0 + key) * 128 + kvh * 32 + dg];
            float vals[4] = {vv.x, vv.y, vv.z, vv.w};
#pragma unroll
            for (int j = 0; j < 4; j++) {
                __nv_bfloat16 hb = __float2bfloat16(vals[j]);
                __nv_bfloat16 lb = __float2bfloat16(vals[j] - __bfloat162float(hb));
                ((__nv_bfloat16*)Vhi)[(size_t)(4 * dg + j) * (2 * VW) + key] = hb;
                ((__nv_bfloat16*)Vlo)[(size_t)(4 * dg + j) * (2 * VW) + key] = lb;
            }
        }
        __syncthreads();

        // ---- S = Q @ K^T (16 x 64 per warp), 3xBF16 ----
        float Sf[8][4];
#pragma unroll
        for (int nt = 0; nt < 8; nt++)
#pragma unroll
            for (int c = 0; c < 4; c++) Sf[nt][c] = 0.0f;

#pragma unroll
        for (int kk = 0; kk < 8; kk++) {     // k=16 per step over HD=128
            const int c0 = kk * 8 + lk;
            uint32_t aH[4], aL[4];
            aH[0] = Qhi[rowA * QW + c0];     aL[0] = Qlo[rowA * QW + c0];
            aH[1] = Qhi[rowB * QW + c0];     aL[1] = Qlo[rowB * QW + c0];
            aH[2] = Qhi[rowA * QW + c0 + 4]; aL[2] = Qlo[rowA * QW + c0 + 4];
            aH[3] = Qhi[rowB * QW + c0 + 4]; aL[3] = Qlo[rowB * QW + c0 + 4];
#pragma unroll
            for (int nt = 0; nt < 8; nt++) {
                const int kr = (nt * 8 + l4) * KW + c0;
                uint32_t bH[2], bL[2];
                bH[0] = Khi[kr];     bH[1] = Khi[kr + 4];
                bL[0] = Klo[kr];     bL[1] = Klo[kr + 4];
                mma_bf16(Sf[nt], aH, bH);
                mma_bf16(Sf[nt], aL, bH);
                mma_bf16(Sf[nt], aH, bL);
            }
        }

        // ---- online softmax (warp-local; rows rowA / rowB) ----
        float mxA = Sf[0][0], mxB = Sf[0][2];
#pragma unroll
        for (int nt = 0; nt < 8; nt++) {
            mxA = fmaxf(mxA, fmaxf(Sf[nt][0], Sf[nt][1]));
            mxB = fmaxf(mxB, fmaxf(Sf[nt][2], Sf[nt][3]));
        }
        mxA = fmaxf(mxA, __shfl_xor_sync(0xffffffffu, mxA, 1));
        mxA = fmaxf(mxA, __shfl_xor_sync(0xffffffffu, mxA, 2));
        mxB = fmaxf(mxB, __shfl_xor_sync(0xffffffffu, mxB, 1));
        mxB = fmaxf(mxB, __shfl_xor_sync(0xffffffffu, mxB, 2));

        float mnA = fmaxf(mA, mxA), mnB = fmaxf(mB, mxB);
        float cA = __expf(mA - mnA), cB = __expf(mB - mnB);
        mA = mnA; mB = mnB;

        // ---- exp + pack P straight into bf16x2 hi/lo A-fragments ----
        uint32_t pH[8][2], pL[8][2];
        float sA = 0.0f, sB = 0.0f;
#pragma unroll
        for (int nt = 0; nt < 8; nt++) {
            float p0 = __expf(Sf[nt][0] - mnA), p1 = __expf(Sf[nt][1] - mnA);
            float p2 = __expf(Sf[nt][2] - mnB), p3 = __expf(Sf[nt][3] - mnB);
            sA += p0 + p1; sB += p2 + p3;
            splitbf2(p0, p1, pH[nt][0], pL[nt][0]);   // row l4
            splitbf2(p2, p3, pH[nt][1], pL[nt][1]);   // row l4+8
        }
        sA += __shfl_xor_sync(0xffffffffu, sA, 1);
        sA += __shfl_xor_sync(0xffffffffu, sA, 2);
        sB += __shfl_xor_sync(0xffffffffu, sB, 1);
        sB += __shfl_xor_sync(0xffffffffu, sB, 2);
        lA = lA * cA + sA;
        lB = lB * cB + sB;

#pragma unroll
        for (int nt = 0; nt < 16; nt++) {
            O[nt][0] *= cA; O[nt][1] *= cA;
            O[nt][2] *= cB; O[nt][3] *= cB;
        }

        // ---- O += P @ V (16 x 128 per warp), 3xBF16, P from registers ----
#pragma unroll
        for (int kt = 0; kt < 4; kt++) {     // 16 keys per step
            uint32_t aH[4], aL[4];
            aH[0] = pH[2 * kt][0];     aL[0] = pL[2 * kt][0];
            aH[1] = pH[2 * kt][1];     aL[1] = pL[2 * kt][1];
            aH[2] = pH[2 * kt + 1][0]; aL[2] = pL[2 * kt + 1][0];
            aH[3] = pH[2 * kt + 1][1]; aL[3] = pL[2 * kt + 1][1];
            const int ck = kt * 8 + lk;
#pragma unroll
            for (int nt = 0; nt < 16; nt++) {
                const int vr = (nt * 8 + l4) * VW + ck;
                uint32_t vH[2], vL[2];
                vH[0] = Vhi[vr];     vH[1] = Vhi[vr + 4];
                vL[0] = Vlo[vr];     vL[1] = Vlo[vr + 4];
                mma_bf16(O[nt], aH, vH);
                mma_bf16(O[nt], aL, vH);
                mma_bf16(O[nt], aH, vL);
            }
        }
    }

    // ---- epilogue: O /= l, write [B*QL, NH*HD] ----
    float iA = 1.0f / lA, iB = 1.0f / lB;
    float* obase = o + ((size_t)(b * QL_ + q0 + rowA)) * (NH_ * HD_) + h * HD_;
#pragma unroll
    for (int nt = 0; nt < 16; nt++) {
        *(float2*)(obase + nt * 8 + 2 * lk) =
            make_float2(O[nt][0] * iA, O[nt][1] * iA);
        *(float2*)(obase + (size_t)8 * (NH_ * HD_) + nt * 8 + 2 * lk) =
            make_float2(O[nt][2] * iB, O[nt][3] * iB);
    }
}

// ---------------- launch ----------------
extern "C" void kernel_launch(void* const* d_in, const int* in_sizes, int n_in,
                              void* d_out, int out_size) {
    const float* noise = (const float*)d_in[0];
    const float* ctx   = (const float*)d_in[1];
    const float* cosT  = (const float*)d_in[2];
    const float* sinT  = (const float*)d_in[3];
    const float* Wq    = (const float*)d_in[4];
    const float* Wk    = (const float*)d_in[5];
    const float* Wv    = (const float*)d_in[6];
    const float* Wo    = (const float*)d_in[7];
    const float* qnw   = (const float*)d_in[8];
    const float* knw   = (const float*)d_in[9];
    float* out = (float*)d_out;

    float *qraw, *kraw, *vraw, *qn, *kn, *ao;
    cudaGetSymbolAddress((void**)&qraw, g_qraw);
    cudaGetSymbolAddress((void**)&kraw, g_kraw);
    cudaGetSymbolAddress((void**)&vraw, g_vraw);
    cudaGetSymbolAddress((void**)&qn,   g_qn);
    cudaGetSymbolAddress((void**)&kn,   g_kn);
    cudaGetSymbolAddress((void**)&ao,   g_ao);

    cudaFuncSetAttribute(flash_bf16_kernel, cudaFuncAttributeMaxDynamicSharedMemorySize,
                         FLASH_SMEM);

    // projections (tf32 tensor cores, 3xTF32 split)
    gemm_tf32_kernel<false><<<dim3(16, 32), 256>>>(noise, nullptr, nullptr, Wq, qraw,
                                                   B_ * QL_, NH_ * HD_);
    gemm_tf32_kernel<true><<<dim3(4, 128), 256>>>(nullptr, ctx, noise, Wk, kraw,
                                                  B_ * KL_, NKV_ * HD_);
    gemm_tf32_kernel<true><<<dim3(4, 128), 256>>>(nullptr, ctx, noise, Wv, vraw,
                                                  B_ * KL_, NKV_ * HD_);
    // norm + rope
    qnorm_rope_kernel<<<B_ * QL_ * NH_, 128>>>(qraw, cosT, sinT, qnw, qn);
    knorm_rope_kernel<<<B_ * KL_ * NKV_, 128>>>(kraw, cosT, sinT, knw, kn);
    // attention (bf16x3, 128q tile, register-resident P)
    flash_bf16_kernel<<<dim3(QL_ / 128, NH_, B_), 256, FLASH_SMEM>>>(qn, kn, vraw, ao);
    // output projection
    gemm_tf32_kernel<false><<<dim3(16, 32), 256>>>(ao, nullptr, nullptr, Wo, out,
                                                   B_ * QL_, NH_ * HD_);
}

// round 17
// speedup vs baseline: 1.5822x; 1.1363x over previous
#include <cuda_runtime.h>
#include <cuda_bf16.h>
#include <cstdint>

// ---------------- problem constants ----------------
#define B_    4
#define QL_   1024
#define CL_   3072
#define KL_   4096      // CL + QL
#define H_    2048
#define NH_   16
#define NKV_  4
#define HD_   128
#define GROUPS_ 4       // NH / NKV

constexpr float EPS_   = 1e-6f;
constexpr float SCALE_ = 0.08838834764831845f; // 128^-0.5

// ---------------- scratch (device globals; no allocations allowed) ----------------
__device__ float g_qraw[(size_t)B_ * QL_ * NH_ * HD_];   // [B*QL, NH*HD]
__device__ float g_kraw[(size_t)B_ * KL_ * NKV_ * HD_];  // [B*KL, NKV*HD]
__device__ float g_vraw[(size_t)B_ * KL_ * NKV_ * HD_];  // [B*KL, NKV*HD]
__device__ float g_qn  [(size_t)B_ * NH_ * QL_ * HD_];   // [B, NH, QL, HD]
__device__ float g_ao  [(size_t)B_ * QL_ * NH_ * HD_];   // [B*QL, NH*HD]
// pre-split bf16 planes (packed bf16x2 words)
__device__ uint32_t g_khi[(size_t)B_ * NKV_ * KL_ * 64];        // [b,kvh,key][dim-word]
__device__ uint32_t g_klo[(size_t)B_ * NKV_ * KL_ * 64];
__device__ uint32_t g_vhi[(size_t)B_ * NKV_ * HD_ * (KL_ / 2)]; // [b,kvh,dim][key-word]
__device__ uint32_t g_vlo[(size_t)B_ * NKV_ * HD_ * (KL_ / 2)];

// ---------------- helpers ----------------
template <bool CONCAT>
__device__ __forceinline__ const float* a_rowptr(const float* __restrict__ A,
                                                 const float* __restrict__ ctx,
                                                 const float* __restrict__ noise,
                                                 int r) {
    if (!CONCAT) return A + (size_t)r * H_;
    int b = r >> 12;        // / KL_
    int p = r & (KL_ - 1);  // % KL_
    return (p < CL_) ? ctx + (size_t)(b * CL_ + p) * H_
                     : noise + (size_t)(b * QL_ + (p - CL_)) * H_;
}

__device__ __forceinline__ uint32_t f2tf32(float x) {
    uint32_t r;
    asm("cvt.rna.tf32.f32 %0, %1;" : "=r"(r) : "f"(x));
    return r;
}

__device__ __forceinline__ void splitf(float x, uint32_t& hi, uint32_t& lo) {
    hi = f2tf32(x);
    lo = f2tf32(x - __uint_as_float(hi));
}

__device__ __forceinline__ void mma_tf32(float* c, const uint32_t* a, const uint32_t* b) {
    asm volatile(
        "mma.sync.aligned.m16n8k8.row.col.f32.tf32.tf32.f32 "
        "{%0,%1,%2,%3}, {%4,%5,%6,%7}, {%8,%9}, {%0,%1,%2,%3};\n"
        : "+f"(c[0]), "+f"(c[1]), "+f"(c[2]), "+f"(c[3])
        : "r"(a[0]), "r"(a[1]), "r"(a[2]), "r"(a[3]), "r"(b[0]), "r"(b[1]));
}

// bf16 pair pack: result lower16 = bf16(x0), upper16 = bf16(x1)
__device__ __forceinline__ uint32_t packbf2(float x0, float x1) {
    uint32_t r;
    asm("cvt.rn.bf16x2.f32 %0, %1, %2;" : "=r"(r) : "f"(x1), "f"(x0));
    return r;
}
// split pair into hi/lo bf16x2 words
__device__ __forceinline__ void splitbf2(float x0, float x1, uint32_t& hi, uint32_t& lo) {
    hi = packbf2(x0, x1);
    float h0 = __uint_as_float(hi << 16);
    float h1 = __uint_as_float(hi & 0xffff0000u);
    lo = packbf2(x0 - h0, x1 - h1);
}

__device__ __forceinline__ void mma_bf16(float* c, const uint32_t* a, const uint32_t* b) {
    asm volatile(
        "mma.sync.aligned.m16n8k16.row.col.f32.bf16.bf16.f32 "
        "{%0,%1,%2,%3}, {%4,%5,%6,%7}, {%8,%9}, {%0,%1,%2,%3};\n"
        : "+f"(c[0]), "+f"(c[1]), "+f"(c[2]), "+f"(c[3])
        : "r"(a[0]), "r"(a[1]), "r"(a[2]), "r"(a[3]), "r"(b[0]), "r"(b[1]));
}

__device__ __forceinline__ void cpa16(uint32_t smem_addr, const void* gptr) {
    asm volatile("cp.async.cg.shared.global [%0], [%1], 16;"
                 :: "r"(smem_addr), "l"(gptr));
}
__device__ __forceinline__ void cpa_commit() {
    asm volatile("cp.async.commit_group;");
}
__device__ __forceinline__ void cpa_wait0() {
    asm volatile("cp.async.wait_group 0;");
}

// ---------------- tf32 tensor-core GEMM (3xTF32 split => ~fp32 accuracy) ----------------
#define APAD 36
#define BPAD 132

template <bool CONCAT>
__global__ __launch_bounds__(256) void gemm_tf32_kernel(
    const float* __restrict__ A, const float* __restrict__ ctx,
    const float* __restrict__ noise, const float* __restrict__ W,
    float* __restrict__ C, int M, int N) {
    __shared__ float As[128 * APAD];
    __shared__ float Bs[32 * BPAD];

    const int tid  = threadIdx.x;
    const int lane = tid & 31;
    const int wid  = tid >> 5;
    const int warp_m = wid & 3;
    const int warp_n = wid >> 2;

    const int row0 = blockIdx.y * 128;
    const int col0 = blockIdx.x * 128;

    const int ka = (tid & 7) * 4;
    const int ar = tid >> 3;
    const int nb = (tid & 31) * 4;
    const int kb = tid >> 5;

    const float* arow[4];
#pragma unroll
    for (int i = 0; i < 4; i++)
        arow[i] = a_rowptr<CONCAT>(A, ctx, noise, row0 + ar + 32 * i);

    const int l4 = lane >> 2;
    const int lk = lane & 3;

    float acc[2][8][4];
#pragma unroll
    for (int mt = 0; mt < 2; mt++)
#pragma unroll
        for (int nt = 0; nt < 8; nt++)
#pragma unroll
            for (int c = 0; c < 4; c++) acc[mt][nt][c] = 0.0f;

    for (int k0 = 0; k0 < H_; k0 += 32) {
        float4 areg[4], breg[4];
#pragma unroll
        for (int i = 0; i < 4; i++)
            areg[i] = *(const float4*)(arow[i] + k0 + ka);
#pragma unroll
        for (int i = 0; i < 4; i++)
            breg[i] = *(const float4*)(W + (size_t)(k0 + kb + 8 * i) * N + col0 + nb);

        __syncthreads();
#pragma unroll
        for (int i = 0; i < 4; i++)
            *(float4*)&As[(ar + 32 * i) * APAD + ka] = areg[i];
#pragma unroll
        for (int i = 0; i < 4; i++)
            *(float4*)&Bs[(kb + 8 * i) * BPAD + nb] = breg[i];
        __syncthreads();

#pragma unroll
        for (int kk = 0; kk < 32; kk += 8) {
            uint32_t ahi[2][4], alo[2][4];
#pragma unroll
            for (int mt = 0; mt < 2; mt++) {
                int r0 = (warp_m * 32 + mt * 16 + l4) * APAD;
                int r1 = r0 + 8 * APAD;
                splitf(As[r0 + kk + lk],     ahi[mt][0], alo[mt][0]);
                splitf(As[r1 + kk + lk],     ahi[mt][1], alo[mt][1]);
                splitf(As[r0 + kk + lk + 4], ahi[mt][2], alo[mt][2]);
                splitf(As[r1 + kk + lk + 4], ahi[mt][3], alo[mt][3]);
            }
            uint32_t bhi[8][2], blo[8][2];
#pragma unroll
            for (int nt = 0; nt < 8; nt++) {
                int cn = warp_n * 64 + nt * 8 + l4;
                splitf(Bs[(kk + lk) * BPAD + cn],     bhi[nt][0], blo[nt][0]);
                splitf(Bs[(kk + lk + 4) * BPAD + cn], bhi[nt][1], blo[nt][1]);
            }
#pragma unroll
            for (int mt = 0; mt < 2; mt++)
#pragma unroll
                for (int nt = 0; nt < 8; nt++) {
                    mma_tf32(acc[mt][nt], ahi[mt], bhi[nt]);
                    mma_tf32(acc[mt][nt], ahi[mt], blo[nt]);
                    mma_tf32(acc[mt][nt], alo[mt], bhi[nt]);
                }
        }
    }

#pragma unroll
    for (int mt = 0; mt < 2; mt++) {
        int r0 = row0 + warp_m * 32 + mt * 16 + l4;
#pragma unroll
        for (int nt = 0; nt < 8; nt++) {
            int cn = col0 + warp_n * 64 + nt * 8 + 2 * lk;
            *(float2*)(C + (size_t)r0 * N + cn) = make_float2(acc[mt][nt][0], acc[mt][nt][1]);
            *(float2*)(C + (size_t)(r0 + 8) * N + cn) = make_float2(acc[mt][nt][2], acc[mt][nt][3]);
        }
    }
}

// ---------------- RMSNorm + RoPE ----------------
__device__ __forceinline__ float block_sum128(float v, float* red) {
#pragma unroll
    for (int o = 16; o; o >>= 1) v += __shfl_xor_sync(0xffffffffu, v, o);
    if ((threadIdx.x & 31) == 0) red[threadIdx.x >> 5] = v;
    __syncthreads();
    return red[0] + red[1] + red[2] + red[3];
}

__global__ __launch_bounds__(128) void qnorm_rope_kernel(
    const float* __restrict__ qraw, const float* __restrict__ cosT,
    const float* __restrict__ sinT, const float* __restrict__ w,
    float* __restrict__ qout) {
    __shared__ float red[4];
    __shared__ float sx[128];
    const int blk = blockIdx.x;
    const int h   = blk & (NH_ - 1);
    const int row = blk >> 4;
    const int b   = row >> 10;
    const int qi  = row & (QL_ - 1);
    const int t   = threadIdx.x;

    float x = qraw[(size_t)row * (NH_ * HD_) + h * HD_ + t];
    float ss = block_sum128(x * x, red);
    float inv = rsqrtf(ss * (1.0f / HD_) + EPS_);
    float xn = x * inv * w[t];
    sx[t] = xn;
    __syncthreads();
    float rot = (t < 64) ? -sx[t + 64] : sx[t - 64];
    int pos = CL_ + qi;
    size_t ci = ((size_t)b * KL_ + pos) * HD_ + t;
    float outv = xn * cosT[ci] + rot * sinT[ci];
    qout[(((size_t)(b * NH_ + h) * QL_) + qi) * HD_ + t] = outv;
}

// K norm+rope, writing packed bf16 hi/lo planes directly.
__global__ __launch_bounds__(128) void knorm_rope_kernel(
    const float* __restrict__ kraw, const float* __restrict__ cosT,
    const float* __restrict__ sinT, const float* __restrict__ w,
    uint32_t* __restrict__ khi, uint32_t* __restrict__ klo) {
    __shared__ float red[4];
    __shared__ float sx[128];
    __shared__ float sxo[128];
    const int blk = blockIdx.x;
    const int kvh = blk & (NKV_ - 1);
    const int row = blk >> 2;
    const int b   = row >> 12;
    const int p   = row & (KL_ - 1);
    const int t   = threadIdx.x;

    float x = kraw[(size_t)row * (NKV_ * HD_) + kvh * HD_ + t];
    float ss = block_sum128(x * x, red);
    float inv = rsqrtf(ss * (1.0f / HD_) + EPS_);
    float xn = x * inv * w[t];
    sx[t] = xn;
    __syncthreads();
    float rot = (t < 64) ? -sx[t + 64] : sx[t - 64];
    size_t ci = ((size_t)b * KL_ + p) * HD_ + t;
    sxo[t] = xn * cosT[ci] + rot * sinT[ci];
    __syncthreads();
    if (t < 64) {
        uint32_t hi, lo;
        splitbf2(sxo[2 * t], sxo[2 * t + 1], hi, lo);
        size_t idx = ((size_t)(b * NKV_ + kvh) * KL_ + p) * 64 + t;
        khi[idx] = hi;
        klo[idx] = lo;
    }
}

// V transpose + bf16 split: vraw [b,key][kvh*128+dim] -> planes [b,kvh,dim][key-word]
__global__ __launch_bounds__(256) void vprep_kernel(
    const float* __restrict__ vraw,
    uint32_t* __restrict__ vhi, uint32_t* __restrict__ vlo) {
    __shared__ uint32_t Shi[128 * 33];
    __shared__ uint32_t Slo[128 * 33];
    const int b   = blockIdx.z;
    const int kvh = blockIdx.y;
    const int k0  = blockIdx.x * 64;
    const int tid = threadIdx.x;
    const float4* vb4 = (const float4*)vraw;

    for (int i = tid; i < 64 * 32; i += 256) {
        int key = i >> 5, c = i & 31;
        float4 v = vb4[(size_t)(b * KL_ + k0 + key) * 128 + kvh * 32 + c];
        float vals[4] = {v.x, v.y, v.z, v.w};
#pragma unroll
        for (int j = 0; j < 4; j++) {
            int dim = 4 * c + j;
            __nv_bfloat16 hb = __float2bfloat16(vals[j]);
            __nv_bfloat16 lb = __float2bfloat16(vals[j] - __bfloat162float(hb));
            ((__nv_bfloat16*)Shi)[dim * 66 + key] = hb;
            ((__nv_bfloat16*)Slo)[dim * 66 + key] = lb;
        }
    }
    __syncthreads();
    size_t vbase = (size_t)(b * NKV_ + kvh) * HD_ * (KL_ / 2);
    for (int o = tid; o < 128 * 32; o += 256) {
        int dim = o >> 5, wv = o & 31;
        size_t gi = vbase + (size_t)dim * (KL_ / 2) + (k0 >> 1) + wv;
        vhi[gi] = Shi[dim * 33 + wv];
        vlo[gi] = Slo[dim * 33 + wv];
    }
}

// ---------------- bf16x3 flash attention (v5: pre-split planes + cp.async dbuf) ----------
// Block: 256 thr = 8 warps. Tile: 128 q x 64 k. Warp w owns q rows [w*16, w*16+16).
// K/V arrive as pre-split bf16 planes; mainloop is pure cp.async 16B copies,
// double-buffered (prefetch distance = one compute phase). Register-resident P.
// smem (words): Qhi 0, Qlo 8704, buf b at 17408 + b*17920:
//   Khi +0 (64x68), Klo +4352, Vhi +8704 (128x36), Vlo +13312.
constexpr int QW = 68;
constexpr int KW = 68;
constexpr int VW = 36;
constexpr int KBUFW = 64 * KW;     // 4352
constexpr int VBUFW = 128 * VW;    // 4608
constexpr int BUFW  = 2 * KBUFW + 2 * VBUFW;  // 17920
constexpr int FLASH_SMEM = (2 * 128 * QW + 2 * BUFW) * 4;  // 212992 B

__global__ __launch_bounds__(256, 1) void flash_bf16_kernel(
    const float* __restrict__ q,
    const uint32_t* __restrict__ khi, const uint32_t* __restrict__ klo,
    const uint32_t* __restrict__ vhi, const uint32_t* __restrict__ vlo,
    float* __restrict__ o) {
    extern __shared__ uint32_t smu[];
    uint32_t* Qhi = smu;
    uint32_t* Qlo = smu + 128 * QW;

    const int b   = blockIdx.z;
    const int h   = blockIdx.y;
    const int q0  = blockIdx.x * 128;
    const int kvh = h >> 2;
    const int tid = threadIdx.x;
    const int lane = tid & 31;
    const int w    = tid >> 5;
    const int l4   = lane >> 2;
    const int lk   = lane & 3;

    const size_t kwbase = (size_t)(b * NKV_ + kvh) * KL_ * 64;
    const size_t vwbase = (size_t)(b * NKV_ + kvh) * HD_ * (KL_ / 2);
    const uint32_t smem0 = (uint32_t)__cvta_generic_to_shared(smu);

    // per-thread cp.async coordinates
    const int krow = tid >> 4;            // 0..15 (+16*j)
    const int kw4  = (tid & 15) * 4;      // K word offset
    const int vdim = tid >> 3;            // 0..31 (+32*j)
    const int vw4  = (tid & 7) * 4;       // V word offset

    auto issue_tile = [&](int k0, int buf) {
        uint32_t base = smem0 + (17408 + buf * BUFW) * 4;
#pragma unroll
        for (int j = 0; j < 4; j++) {
            int r = krow + 16 * j;
            uint32_t soff = (r * KW + kw4) * 4;
            size_t g = kwbase + (size_t)(k0 + r) * 64 + kw4;
            cpa16(base + soff,                khi + g);
            cpa16(base + KBUFW * 4 + soff,    klo + g);
        }
#pragma unroll
        for (int j = 0; j < 4; j++) {
            int d = vdim + 32 * j;
            uint32_t soff = (d * VW + vw4) * 4;
            size_t g = vwbase + (size_t)d * (KL_ / 2) + (k0 >> 1) + vw4;
            cpa16(base + 2 * KBUFW * 4 + soff,             vhi + g);
            cpa16(base + (2 * KBUFW + VBUFW) * 4 + soff,   vlo + g);
        }
        cpa_commit();
    };

    // kick off tile 0
    issue_tile(0, 0);

    // ---- load Q tile [128,128]: scale, split into bf16 hi/lo planes ----
    const float4* qsrc = (const float4*)(q + (((size_t)(b * NH_ + h) * QL_ + q0) * HD_));
    for (int i = tid; i < 128 * 32; i += 256) {
        int r = i >> 5, c = i & 31;
        float4 v = qsrc[i];
        uint32_t h0, l0, h1, l1;
        splitbf2(v.x * SCALE_, v.y * SCALE_, h0, l0);
        splitbf2(v.z * SCALE_, v.w * SCALE_, h1, l1);
        *(uint2*)&Qhi[r * QW + 2 * c] = make_uint2(h0, h1);
        *(uint2*)&Qlo[r * QW + 2 * c] = make_uint2(l0, l1);
    }

    float mA = -3.0e38f, mB = -3.0e38f, lA = 0.0f, lB = 0.0f;
    float O[16][4];
#pragma unroll
    for (int nt = 0; nt < 16; nt++)
#pragma unroll
        for (int c = 0; c < 4; c++) O[nt][c] = 0.0f;

    const int rowA = w * 16 + l4;
    const int rowB = rowA + 8;

    for (int t = 0; t < KL_ / 64; t++) {
        cpa_wait0();
        __syncthreads();   // tile t visible to all; prev compute done everywhere
        if (t + 1 < KL_ / 64) issue_tile((t + 1) * 64, (t + 1) & 1);

        const uint32_t* Khi = smu + 17408 + (t & 1) * BUFW;
        const uint32_t* Klo = Khi + KBUFW;
        const uint32_t* Vhi = Klo + KBUFW;
        const uint32_t* Vlo = Vhi + VBUFW;

        // ---- S = Q @ K^T (16 x 64 per warp), 3xBF16 ----
        float Sf[8][4];
#pragma unroll
        for (int nt = 0; nt < 8; nt++)
#pragma unroll
            for (int c = 0; c < 4; c++) Sf[nt][c] = 0.0f;

#pragma unroll
        for (int kk = 0; kk < 8; kk++) {     // k=16 per step over HD=128
            const int c0 = kk * 8 + lk;
            uint32_t aH[4], aL[4];
            aH[0] = Qhi[rowA * QW + c0];     aL[0] = Qlo[rowA * QW + c0];
            aH[1] = Qhi[rowB * QW + c0];     aL[1] = Qlo[rowB * QW + c0];
            aH[2] = Qhi[rowA * QW + c0 + 4]; aL[2] = Qlo[rowA * QW + c0 + 4];
            aH[3] = Qhi[rowB * QW + c0 + 4]; aL[3] = Qlo[rowB * QW + c0 + 4];
#pragma unroll
            for (int nt = 0; nt < 8; nt++) {
                const int kr = (nt * 8 + l4) * KW + c0;
                uint32_t bH[2], bL[2];
                bH[0] = Khi[kr];     bH[1] = Khi[kr + 4];
                bL[0] = Klo[kr];     bL[1] = Klo[kr + 4];
                mma_bf16(Sf[nt], aH, bH);
                mma_bf16(Sf[nt], aL, bH);
                mma_bf16(Sf[nt], aH, bL);
            }
        }

        // ---- online softmax (warp-local; rows rowA / rowB) ----
        float mxA = Sf[0][0], mxB = Sf[0][2];
#pragma unroll
        for (int nt = 0; nt < 8; nt++) {
            mxA = fmaxf(mxA, fmaxf(Sf[nt][0], Sf[nt][1]));
            mxB = fmaxf(mxB, fmaxf(Sf[nt][2], Sf[nt][3]));
        }
        mxA = fmaxf(mxA, __shfl_xor_sync(0xffffffffu, mxA, 1));
        mxA = fmaxf(mxA, __shfl_xor_sync(0xffffffffu, mxA, 2));
        mxB = fmaxf(mxB, __shfl_xor_sync(0xffffffffu, mxB, 1));
        mxB = fmaxf(mxB, __shfl_xor_sync(0xffffffffu, mxB, 2));

        float mnA = fmaxf(mA, mxA), mnB = fmaxf(mB, mxB);
        float cA = __expf(mA - mnA), cB = __expf(mB - mnB);
        mA = mnA; mB = mnB;

        // ---- exp + pack P straight into bf16x2 hi/lo A-fragments ----
        uint32_t pH[8][2], pL[8][2];
        float sA = 0.0f, sB = 0.0f;
#pragma unroll
        for (int nt = 0; nt < 8; nt++) {
            float p0 = __expf(Sf[nt][0] - mnA), p1 = __expf(Sf[nt][1] - mnA);
            float p2 = __expf(Sf[nt][2] - mnB), p3 = __expf(Sf[nt][3] - mnB);
            sA += p0 + p1; sB += p2 + p3;
            splitbf2(p0, p1, pH[nt][0], pL[nt][0]);   // row l4
            splitbf2(p2, p3, pH[nt][1], pL[nt][1]);   // row l4+8
        }
        sA += __shfl_xor_sync(0xffffffffu, sA, 1);
        sA += __shfl_xor_sync(0xffffffffu, sA, 2);
        sB += __shfl_xor_sync(0xffffffffu, sB, 1);
        sB += __shfl_xor_sync(0xffffffffu, sB, 2);
        lA = lA * cA + sA;
        lB = lB * cB + sB;

#pragma unroll
        for (int nt = 0; nt < 16; nt++) {
            O[nt][0] *= cA; O[nt][1] *= cA;
            O[nt][2] *= cB; O[nt][3] *= cB;
        }

        // ---- O += P @ V (16 x 128 per warp), 3xBF16, P from registers ----
#pragma unroll
        for (int kt = 0; kt < 4; kt++) {     // 16 keys per step
            uint32_t aH[4], aL[4];
            aH[0] = pH[2 * kt][0];     aL[0] = pL[2 * kt][0];
            aH[1] = pH[2 * kt][1];     aL[1] = pL[2 * kt][1];
            aH[2] = pH[2 * kt + 1][0]; aL[2] = pL[2 * kt + 1][0];
            aH[3] = pH[2 * kt + 1][1]; aL[3] = pL[2 * kt + 1][1];
            const int ck = kt * 8 + lk;
#pragma unroll
            for (int nt = 0; nt < 16; nt++) {
                const int vr = (nt * 8 + l4) * VW + ck;
                uint32_t vH[2], vL[2];
                vH[0] = Vhi[vr];     vH[1] = Vhi[vr + 4];
                vL[0] = Vlo[vr];     vL[1] = Vlo[vr + 4];
                mma_bf16(O[nt], aH, vH);
                mma_bf16(O[nt], aL, vH);
                mma_bf16(O[nt], aH, vL);
            }
        }
    }

    // ---- epilogue: O /= l, write [B*QL, NH*HD] ----
    float iA = 1.0f / lA, iB = 1.0f / lB;
    float* obase = o + ((size_t)(b * QL_ + q0 + rowA)) * (NH_ * HD_) + h * HD_;
#pragma unroll
    for (int nt = 0; nt < 16; nt++) {
        *(float2*)(obase + nt * 8 + 2 * lk) =
            make_float2(O[nt][0] * iA, O[nt][1] * iA);
        *(float2*)(obase + (size_t)8 * (NH_ * HD_) + nt * 8 + 2 * lk) =
            make_float2(O[nt][2] * iB, O[nt][3] * iB);
    }
}

// ---------------- launch ----------------
extern "C" void kernel_launch(void* const* d_in, const int* in_sizes, int n_in,
                              void* d_out, int out_size) {
    const float* noise = (const float*)d_in[0];
    const float* ctx   = (const float*)d_in[1];
    const float* cosT  = (const float*)d_in[2];
    const float* sinT  = (const float*)d_in[3];
    const float* Wq    = (const float*)d_in[4];
    const float* Wk    = (const float*)d_in[5];
    const float* Wv    = (const float*)d_in[6];
    const float* Wo    = (const float*)d_in[7];
    const float* qnw   = (const float*)d_in[8];
    const float* knw   = (const float*)d_in[9];
    float* out = (float*)d_out;

    float *qraw, *kraw, *vraw, *qn, *ao;
    uint32_t *khi, *klo, *vhi, *vlo;
    cudaGetSymbolAddress((void**)&qraw, g_qraw);
    cudaGetSymbolAddress((void**)&kraw, g_kraw);
    cudaGetSymbolAddress((void**)&vraw, g_vraw);
    cudaGetSymbolAddress((void**)&qn,   g_qn);
    cudaGetSymbolAddress((void**)&ao,   g_ao);
    cudaGetSymbolAddress((void**)&khi,  g_khi);
    cudaGetSymbolAddress((void**)&klo,  g_klo);
    cudaGetSymbolAddress((void**)&vhi,  g_vhi);
    cudaGetSymbolAddress((void**)&vlo,  g_vlo);

    cudaFuncSetAttribute(flash_bf16_kernel, cudaFuncAttributeMaxDynamicSharedMemorySize,
                         FLASH_SMEM);

    // projections (tf32 tensor cores, 3xTF32 split)
    gemm_tf32_kernel<false><<<dim3(16, 32), 256>>>(noise, nullptr, nullptr, Wq, qraw,
                                                   B_ * QL_, NH_ * HD_);
    gemm_tf32_kernel<true><<<dim3(4, 128), 256>>>(nullptr, ctx, noise, Wk, kraw,
                                                  B_ * KL_, NKV_ * HD_);
    gemm_tf32_kernel<true><<<dim3(4, 128), 256>>>(nullptr, ctx, noise, Wv, vraw,
                                                  B_ * KL_, NKV_ * HD_);
    // norm + rope (+ K plane split); V plane transpose/split
    qnorm_rope_kernel<<<B_ * QL_ * NH_, 128>>>(qraw, cosT, sinT, qnw, qn);
    knorm_rope_kernel<<<B_ * KL_ * NKV_, 128>>>(kraw, cosT, sinT, knw, khi, klo);
    vprep_kernel<<<dim3(KL_ / 64, NKV_, B_), 256>>>(vraw, vhi, vlo);
    // attention (bf16x3, pre-split planes, cp.async double buffer, register P)
    flash_bf16_kernel<<<dim3(QL_ / 128, NH_, B_), 256, FLASH_SMEM>>>(qn, khi, klo,
                                                                     vhi, vlo, ao);
    // output projection
    gemm_tf32_kernel<false><<<dim3(16, 32), 256>>>(ao, nullptr, nullptr, Wo, out,
                                                   B_ * QL_, NH_ * HD_);
}